// round 4
// baseline (speedup 1.0000x reference)
#include <cuda_runtime.h>
#include <cuda_bf16.h>

// out[row[e]] += values[e] * x[col[e]],  row sorted ascending.
// E = 1.6M, N = 100k, D = 64.
//
// Kernel 1: edge-parallel CSR offset build (boundary detection on sorted row).
// Kernel 2: one warp per row; lane owns a float2 feature slice.
//           col/val loaded cooperatively (1 coalesced LDG per 32 edges each)
//           and broadcast via shfl -> halves L1 wavefronts per edge.

#define N_NODES 100000
#define D_FEAT 64

__device__ int g_row_ptr[N_NODES + 1];

__global__ void __launch_bounds__(256) build_row_ptr_kernel(
    const int* __restrict__ row, int n_edges, int n_nodes)
{
    int e = blockIdx.x * blockDim.x + threadIdx.x;
    if (e >= n_edges) return;
    int r = row[e];
    int prev = (e == 0) ? -1 : row[e - 1];
    // lower_bound(q) == e for all q in (prev, r]
    for (int q = prev + 1; q <= r; ++q) g_row_ptr[q] = e;
    if (e == n_edges - 1) {
        // tail: rows beyond the last edge's row (and the sentinel) -> n_edges
        for (int q = r + 1; q <= n_nodes; ++q) g_row_ptr[q] = n_edges;
    }
}

__global__ void __launch_bounds__(256) spmm_row_warp_kernel(
    const int* __restrict__ col,
    const float* __restrict__ val,
    const float* __restrict__ x,
    float* __restrict__ out,
    int n_nodes)
{
    int r = (blockIdx.x * blockDim.x + threadIdx.x) >> 5;
    if (r >= n_nodes) return;
    int lane = threadIdx.x & 31;

    int s = g_row_ptr[r];
    int e = g_row_ptr[r + 1];

    const float2* __restrict__ x2 = (const float2*)x;
    float2 acc = make_float2(0.f, 0.f);

    for (int base = s; base < e; base += 32) {
        int idx = base + lane;
        int   c_l = 0;
        float v_l = 0.f;
        if (idx < e) {
            c_l = __ldg(&col[idx]);   // one coalesced 128B load per 32 edges
            v_l = __ldg(&val[idx]);
        }
        int cnt = min(32, e - base);
        #pragma unroll 4
        for (int j = 0; j < cnt; ++j) {
            int   c = __shfl_sync(0xffffffffu, c_l, j);
            float v = __shfl_sync(0xffffffffu, v_l, j);
            float2 xv = __ldg(&x2[(size_t)c * (D_FEAT / 2) + lane]);  // 256B coalesced gather
            acc.x = fmaf(v, xv.x, acc.x);
            acc.y = fmaf(v, xv.y, acc.y);
        }
    }

    ((float2*)out)[(size_t)r * (D_FEAT / 2) + lane] = acc;
}

extern "C" void kernel_launch(void* const* d_in, const int* in_sizes, int n_in,
                              void* d_out, int out_size) {
    const int*   row = (const int*)d_in[0];
    const int*   col = (const int*)d_in[1];
    const float* val = (const float*)d_in[2];
    const float* x   = (const float*)d_in[3];
    float*       out = (float*)d_out;

    int n_edges = in_sizes[0];
    int n_nodes = in_sizes[3] / D_FEAT;

    {
        int threads = 256;
        int blocks = (n_edges + threads - 1) / threads;
        build_row_ptr_kernel<<<blocks, threads>>>(row, n_edges, n_nodes);
    }
    {
        int threads = 256;  // 8 warps/block, 1 row per warp
        long warps = n_nodes;
        int blocks = (int)((warps * 32 + threads - 1) / threads);
        spmm_row_warp_kernel<<<blocks, threads>>>(col, val, x, out, n_nodes);
    }
}

// round 5
// speedup vs baseline: 1.1128x; 1.1128x over previous
#include <cuda_runtime.h>
#include <cuda_bf16.h>

// out[row[e]] += values[e] * x[col[e]],  row sorted ascending.
// E = 1.6M, N = 100k, D = 64.
//
// Kernel 1: edge-parallel CSR offset build (boundary detect on sorted row). ~0.5us.
// Kernel 2: one warp per row, TWO edges per warp-iteration:
//           half-warp h (lanes 16h..16h+15) processes edge s+2j+h.
//           Each lane owns 4 features (float4, LDG.128 -> 256B/edge gather).
//           Cross-half shfl_xor reduce once at the end. ~3.9 issues/edge.

#define N_NODES 100000
#define D_FEAT 64

__device__ int g_row_ptr[N_NODES + 1];

__global__ void __launch_bounds__(256) build_row_ptr_kernel(
    const int* __restrict__ row, int n_edges, int n_nodes)
{
    int e = blockIdx.x * blockDim.x + threadIdx.x;
    if (e >= n_edges) return;
    int r = row[e];
    int prev = (e == 0) ? -1 : row[e - 1];
    for (int q = prev + 1; q <= r; ++q) g_row_ptr[q] = e;   // lower_bound fill
    if (e == n_edges - 1) {
        for (int q = r + 1; q <= n_nodes; ++q) g_row_ptr[q] = n_edges;
    }
}

__global__ void __launch_bounds__(256) spmm_row_warp_kernel(
    const int* __restrict__ col,
    const float* __restrict__ val,
    const float* __restrict__ x,
    float* __restrict__ out,
    int n_nodes)
{
    int r = (blockIdx.x * blockDim.x + threadIdx.x) >> 5;
    if (r >= n_nodes) return;
    int lane = threadIdx.x & 31;
    int half = lane >> 4;          // which edge of the pair this lane works on
    int fl   = lane & 15;          // feature lane: owns feats [4*fl, 4*fl+4)

    int s = g_row_ptr[r];
    int e = g_row_ptr[r + 1];

    const float4* __restrict__ x4 = (const float4*)x;
    float4 acc = make_float4(0.f, 0.f, 0.f, 0.f);

    #pragma unroll 4
    for (int i = s + half; i < e; i += 2) {
        int   c = __ldg(&col[i]);                     // 2 addrs/warp, 1 sector
        float v = __ldg(&val[i]);
        float4 xv = __ldg(&x4[(size_t)c * (D_FEAT / 4) + fl]);  // 256B coalesced gather
        acc.x = fmaf(v, xv.x, acc.x);
        acc.y = fmaf(v, xv.y, acc.y);
        acc.z = fmaf(v, xv.z, acc.z);
        acc.w = fmaf(v, xv.w, acc.w);
    }

    // combine the two half-warp partial sums (even edges + odd edges)
    acc.x += __shfl_xor_sync(0xffffffffu, acc.x, 16);
    acc.y += __shfl_xor_sync(0xffffffffu, acc.y, 16);
    acc.z += __shfl_xor_sync(0xffffffffu, acc.z, 16);
    acc.w += __shfl_xor_sync(0xffffffffu, acc.w, 16);

    if (half == 0) {
        ((float4*)out)[(size_t)r * (D_FEAT / 4) + fl] = acc;
    }
}

extern "C" void kernel_launch(void* const* d_in, const int* in_sizes, int n_in,
                              void* d_out, int out_size) {
    const int*   row = (const int*)d_in[0];
    const int*   col = (const int*)d_in[1];
    const float* val = (const float*)d_in[2];
    const float* x   = (const float*)d_in[3];
    float*       out = (float*)d_out;

    int n_edges = in_sizes[0];
    int n_nodes = in_sizes[3] / D_FEAT;

    {
        int threads = 256;
        int blocks = (n_edges + threads - 1) / threads;
        build_row_ptr_kernel<<<blocks, threads>>>(row, n_edges, n_nodes);
    }
    {
        int threads = 256;  // 8 warps/block, 1 row per warp
        long warps = n_nodes;
        int blocks = (int)((warps * 32 + threads - 1) / threads);
        spmm_row_warp_kernel<<<blocks, threads>>>(col, val, x, out, n_nodes);
    }
}